// round 7
// baseline (speedup 1.0000x reference)
#include <cuda_runtime.h>

// OpticalFlow dense_image_warp: image [8,512,512,16] f32, flow [8,512,512,2] f32
// out[b,y,x,c] = bilinear sample at (y - flow[...,0], x - flow[...,1]), edge clamp.
//
// R2: 4 threads/pixel channel-parallel (59.4us). R3 ILP / R4 prefetch: neutral or
//     worse -> limiter is L1tex wavefront service (within-LDG replays ~2cyc/wf),
//     not warp-side latency.
// R6: 8 lanes/pixel butterfly. One LDG.128 covers tl||tr as a contiguous 128B
//     segment (8 lanes x 16B), second LDG covers bl||br. 2 gather LDGs per
//     4-pixel warp instead of 4 scattered ones per 8 pixels: fewer distinct
//     lines per instruction + cross-pixel line sharing. Vertical blend in-lane,
//     horizontal blend via shfl_xor(4). Half-warp coalesced 256B store.

#define B 8
#define H 512
#define W 512
#define HW (H * W)
#define NPIX (B * HW)
#define TOTAL_T (NPIX * 8)   // 8 lanes per pixel

__global__ __launch_bounds__(256) void warp_kernel(
    const float* __restrict__ image,
    const float* __restrict__ flow,
    float* __restrict__ out)
{
    int t = blockIdx.x * blockDim.x + threadIdx.x;

    int pix = t >> 3;        // pixel index
    int h   = t & 7;         // 16B chunk within the 128B (tl||tr) row segment
    int side = h >> 2;       // 0 = left corner column, 1 = right

    int b = pix >> 18;
    int p = pix & (HW - 1);
    int y = p >> 9;
    int x = p & 511;

    // 4 pixels/warp x 8B contiguous = 32B -> single-line broadcast load
    float2 f = __ldg(((const float2*)flow) + pix);
    float qy = (float)y - f.x;
    float qx = (float)x - f.y;

    float fy = fminf(fmaxf(floorf(qy), 0.0f), (float)(H - 2));
    float fx = fminf(fmaxf(floorf(qx), 0.0f), (float)(W - 2));
    float ay = fminf(fmaxf(qy - fy, 0.0f), 1.0f);
    float ax = fminf(fmaxf(qx - fx, 0.0f), 1.0f);
    int iy = (int)fy;
    int ix = (int)fx;

    // float4 units: (tl||tr) top row segment = 8 x 16B starting at pixel (iy,ix)
    const float4* base = (const float4*)image + (size_t)b * (HW * 4);
    int o_top = (iy * W + ix) * 4 + h;
    int o_bot = o_top + W * 4;

    float4 top = __ldg(base + o_top);
    float4 bot = __ldg(base + o_bot);

    // vertical blend in-lane
    float4 v;
    v.x = top.x + ay * (bot.x - top.x);
    v.y = top.y + ay * (bot.y - top.y);
    v.z = top.z + ay * (bot.z - top.z);
    v.w = top.w + ay * (bot.w - top.w);

    // horizontal blend via butterfly: partner lane holds the other corner column
    float4 o;
    o.x = __shfl_xor_sync(0xffffffffu, v.x, 4);
    o.y = __shfl_xor_sync(0xffffffffu, v.y, 4);
    o.z = __shfl_xor_sync(0xffffffffu, v.z, 4);
    o.w = __shfl_xor_sync(0xffffffffu, v.w, 4);

    // left = column ix, right = column ix+1 (order by side)
    float lx = side ? o.x : v.x, rx = side ? v.x : o.x;
    float ly = side ? o.y : v.y, ry = side ? v.y : o.y;
    float lz = side ? o.z : v.z, rz = side ? v.z : o.z;
    float lw = side ? o.w : v.w, rw = side ? v.w : o.w;

    float4 r;
    r.x = lx + ax * (rx - lx);
    r.y = ly + ax * (ry - ly);
    r.z = lz + ax * (rz - lz);
    r.w = lw + ax * (rw - lw);

    // lanes h<4 store: per warp 16 lanes x 16B = 256B contiguous (4 pixels)
    if (side == 0)
        __stcs(((float4*)out) + ((size_t)pix * 4 + h), r);
}

extern "C" void kernel_launch(void* const* d_in, const int* in_sizes, int n_in,
                              void* d_out, int out_size)
{
    const float* image = (const float*)d_in[0];
    const float* flow  = (const float*)d_in[1];
    float* out = (float*)d_out;

    int threads = 256;
    int blocks = TOTAL_T / threads;   // 65536
    warp_kernel<<<blocks, threads>>>(image, flow, out);
}

// round 8
// speedup vs baseline: 1.6182x; 1.6182x over previous
#include <cuda_runtime.h>

// OpticalFlow dense_image_warp: image [8,512,512,16] f32, flow [8,512,512,2] f32
// out[b,y,x,c] = bilinear sample at (y - flow[...,0], x - flow[...,1]), edge clamp.
//
// R2: 4 threads/pixel channel-parallel (59.4us) — best memory pattern so far.
// R3: +2px/thread ILP regressed via occupancy loss (38 regs -> occ 64%).
// R6: 8-lane butterfly regressed via 2.4x instruction overhead.
// R7: R3 retried with the occupancy confound removed: __launch_bounds__(256,8)
//     caps regs at 32 (2048 thr/SM), all 32-bit indexing (no IMAD.WIDE),
//     flow via __ldcs, out via __stcs. 9 front-batched loads in flight/thread.

#define B 8
#define H 512
#define W 512
#define HW (H * W)
#define NPIX (B * HW)
#define NTHREADS_TOTAL (NPIX * 2)   // 4 threads per 2-pixel pair

__device__ __forceinline__ float4 blend4(float4 tl, float4 tr, float4 bl, float4 br,
                                         float ax, float ay)
{
    float4 r;
    float tp, bt;
    tp = tl.x + ax * (tr.x - tl.x); bt = bl.x + ax * (br.x - bl.x); r.x = tp + ay * (bt - tp);
    tp = tl.y + ax * (tr.y - tl.y); bt = bl.y + ax * (br.y - bl.y); r.y = tp + ay * (bt - tp);
    tp = tl.z + ax * (tr.z - tl.z); bt = bl.z + ax * (br.z - bl.z); r.z = tp + ay * (bt - tp);
    tp = tl.w + ax * (tr.w - tl.w); bt = bl.w + ax * (br.w - bl.w); r.w = tp + ay * (bt - tp);
    return r;
}

__global__ __launch_bounds__(256, 8) void warp_kernel(
    const float* __restrict__ image,
    const float* __restrict__ flow,
    float* __restrict__ out)
{
    unsigned t = blockIdx.x * blockDim.x + threadIdx.x;

    unsigned g  = t & 3u;        // channel group 0..3
    unsigned pp = t >> 2;        // pixel-pair index
    unsigned pix0 = pp << 1;     // even pixel; pix1 = pix0+1 (same row: W even)

    unsigned b = pix0 >> 18;
    unsigned p = pix0 & (HW - 1);
    unsigned y = p >> 9;
    unsigned x = p & 511u;       // even; x+1 < 512 always

    // both pixels' flow in one float4; streamed (no reuse)
    float4 f = __ldcs(((const float4*)flow) + pp);

    // pixel 0
    float qy0 = (float)y - f.x;
    float qx0 = (float)x - f.y;
    float fy0 = fminf(fmaxf(floorf(qy0), 0.0f), (float)(H - 2));
    float fx0 = fminf(fmaxf(floorf(qx0), 0.0f), (float)(W - 2));
    float ay0 = fminf(fmaxf(qy0 - fy0, 0.0f), 1.0f);
    float ax0 = fminf(fmaxf(qx0 - fx0, 0.0f), 1.0f);
    int iy0 = (int)fy0, ix0 = (int)fx0;

    // pixel 1
    float qy1 = (float)y - f.z;
    float qx1 = (float)(x + 1) - f.w;
    float fy1 = fminf(fmaxf(floorf(qy1), 0.0f), (float)(H - 2));
    float fx1 = fminf(fmaxf(floorf(qx1), 0.0f), (float)(W - 2));
    float ay1 = fminf(fmaxf(qy1 - fy1, 0.0f), 1.0f);
    float ax1 = fminf(fmaxf(qx1 - fx1, 0.0f), 1.0f);
    int iy1 = (int)fy1, ix1 = (int)fx1;

    // 32-bit float4 indexing throughout (image = 33.5M float4 < 2^31)
    const float4* base = (const float4*)image + b * (unsigned)(HW * 4);
    unsigned a_tl = (unsigned)(iy0 * W + ix0) * 4u + g;
    unsigned a_bl = a_tl + W * 4u;
    unsigned b_tl = (unsigned)(iy1 * W + ix1) * 4u + g;
    unsigned b_bl = b_tl + W * 4u;

    // front-batch all 8 gathers (plus flow already in flight: 9 loads)
    float4 tl0 = __ldg(base + a_tl);
    float4 tr0 = __ldg(base + a_tl + 4);
    float4 bl0 = __ldg(base + a_bl);
    float4 br0 = __ldg(base + a_bl + 4);
    float4 tl1 = __ldg(base + b_tl);
    float4 tr1 = __ldg(base + b_tl + 4);
    float4 bl1 = __ldg(base + b_bl);
    float4 br1 = __ldg(base + b_bl + 4);

    float4 r0 = blend4(tl0, tr0, bl0, br0, ax0, ay0);
    float4 r1 = blend4(tl1, tr1, bl1, br1, ax1, ay1);

    unsigned o0 = pix0 * 4u + g;          // out float4 index, 32-bit
    __stcs(((float4*)out) + o0, r0);
    __stcs(((float4*)out) + o0 + 4u, r1);
}

extern "C" void kernel_launch(void* const* d_in, const int* in_sizes, int n_in,
                              void* d_out, int out_size)
{
    const float* image = (const float*)d_in[0];
    const float* flow  = (const float*)d_in[1];
    float* out = (float*)d_out;

    int threads = 256;
    int blocks = NTHREADS_TOTAL / threads;   // 16384
    warp_kernel<<<blocks, threads>>>(image, flow, out);
}